// round 16
// baseline (speedup 1.0000x reference)
#include <cuda_runtime.h>
#include <cuda_bf16.h>
#include <cstdint>

#define BB 8
#define NN 2048
#define DD 128
#define LOG2E 1.44269504f
#define NW (NN/32)
#define SPLIT 2
#define PSTR 40      // P smem row stride (bf16)
#define HSTR 136     // H smem row stride (bf16)
#define PBUFB (64*PSTR*2)
#define HBUFB (32*HSTR*2)

// ---------------- device scratch ----------------
__device__ unsigned short g_hcb [BB*NN*DD];   // compacted h, bf16 (padded rows 0)
__device__ unsigned       g_eln [BB*NN];      // packed (bf16 e^{.2el}<<16)|bf16 e^{el}
__device__ unsigned short g_er1c[BB*NN];      // bf16 e^{er}
__device__ unsigned short g_er2c[BB*NN];      // bf16 e^{.2er}
__device__ int            g_act [BB*NN];
__device__ int            g_posm[BB*NN];
__device__ int            g_cnt [BB];
__device__ unsigned       g_adjc[(size_t)BB*NN*NW];
__device__ float          g_pacc[(size_t)SPLIT*BB*NN*DD];
__device__ float          g_psumP[SPLIT][BB*NN];

// ---- helpers ----
__device__ __forceinline__ unsigned hmul2u(unsigned a, unsigned b) {
    __nv_bfloat162 r = __hmul2(*reinterpret_cast<__nv_bfloat162*>(&a),
                               *reinterpret_cast<__nv_bfloat162*>(&b));
    return *reinterpret_cast<unsigned*>(&r);
}
__device__ __forceinline__ unsigned hmax2u(unsigned a, unsigned b) {
    __nv_bfloat162 r = __hmax2(*reinterpret_cast<__nv_bfloat162*>(&a),
                               *reinterpret_cast<__nv_bfloat162*>(&b));
    return *reinterpret_cast<unsigned*>(&r);
}
__device__ __forceinline__ unsigned bpack(float x, float y) {
    __nv_bfloat162 r = __float22bfloat162_rn(make_float2(x, y));
    return *reinterpret_cast<unsigned*>(&r);
}
__device__ __forceinline__ void ldsm_x4(unsigned& r0, unsigned& r1,
                                        unsigned& r2, unsigned& r3, unsigned addr) {
    asm volatile("ldmatrix.sync.aligned.m8n8.x4.shared.b16 {%0,%1,%2,%3}, [%4];"
                 : "=r"(r0), "=r"(r1), "=r"(r2), "=r"(r3) : "r"(addr));
}
__device__ __forceinline__ void ldsm_x4_t(unsigned& r0, unsigned& r1,
                                          unsigned& r2, unsigned& r3, unsigned addr) {
    asm volatile("ldmatrix.sync.aligned.m8n8.x4.trans.shared.b16 {%0,%1,%2,%3}, [%4];"
                 : "=r"(r0), "=r"(r1), "=r"(r2), "=r"(r3) : "r"(addr));
}
__device__ __forceinline__ void mma_bf16(float4& d, unsigned a0, unsigned a1,
                                         unsigned a2, unsigned a3,
                                         unsigned b0, unsigned b1) {
    asm volatile("mma.sync.aligned.m16n8k16.row.col.f32.bf16.bf16.f32 "
        "{%0,%1,%2,%3}, {%4,%5,%6,%7}, {%8,%9}, {%0,%1,%2,%3};"
        : "+f"(d.x), "+f"(d.y), "+f"(d.z), "+f"(d.w)
        : "r"(a0), "r"(a1), "r"(a2), "r"(a3), "r"(b0), "r"(b1));
}
#define CP_ASYNC16(dst, src) \
    asm volatile("cp.async.cg.shared.global [%0], [%1], 16;" :: "r"(dst), "l"(src))
#define CP_COMMIT asm volatile("cp.async.commit_group;" ::: "memory")
#define CP_WAIT0  asm volatile("cp.async.wait_group 0;" ::: "memory")

// ---------------- K1: deterministic compaction ----------------
__global__ void k1_compact(const int* __restrict__ nm) {
    int b = blockIdx.x, t = threadIdx.x;
    __shared__ int part[256];
    const int* m = nm + b*NN;
    int base = t*8, flags[8], c = 0;
#pragma unroll
    for (int k = 0; k < 8; k++) { flags[k] = (m[base+k] != 0); c += flags[k]; }
    part[t] = c; __syncthreads();
    for (int off = 1; off < 256; off <<= 1) {
        int add = (t >= off) ? part[t-off] : 0;
        __syncthreads(); part[t] += add; __syncthreads();
    }
    int pos = part[t] - c;
#pragma unroll
    for (int k = 0; k < 8; k++) {
        if (flags[k]) { g_act[b*NN + pos] = base + k; g_posm[b*NN + base + k] = pos; pos++; }
        else g_posm[b*NN + base + k] = -1;
    }
    if (t == 255) g_cnt[b] = part[255];
}

// ---------------- K2: h = x_active @ W over compacted rows ------------------
__global__ __launch_bounds__(128) void k2_gemm(
    const float* __restrict__ x, const float* __restrict__ W,
    const float* __restrict__ a_l, const float* __restrict__ a_r)
{
    int b = blockIdx.y;
    int cnt = g_cnt[b];
    int c0 = blockIdx.x * 32;
    if (c0 >= cnt) return;

    __shared__ float xs[32][DD];
    int tid = threadIdx.x, tx = tid & 31, ty = tid >> 5;

#pragma unroll 4
    for (int i = 0; i < 32; i++) {
        int ii = c0 + i;
        int row = g_act[b*NN + ((ii < cnt) ? ii : (cnt - 1))];
        xs[i][tid] = x[((size_t)b*NN + row)*DD + tid];
    }
    __syncthreads();

    float4 acc[8];
#pragma unroll
    for (int r = 0; r < 8; r++) acc[r] = make_float4(0.f,0.f,0.f,0.f);

    const float4* W4 = reinterpret_cast<const float4*>(W);
#pragma unroll 4
    for (int k = 0; k < DD; k++) {
        float4 w4 = W4[k*32 + tx];
#pragma unroll
        for (int r = 0; r < 8; r++) {
            float xv = xs[ty*8 + r][k];
            acc[r].x += xv*w4.x; acc[r].y += xv*w4.y;
            acc[r].z += xv*w4.z; acc[r].w += xv*w4.w;
        }
    }

    float4 alv = *reinterpret_cast<const float4*>(a_l + tx*4);
    float4 arv = *reinterpret_cast<const float4*>(a_r + tx*4);
#pragma unroll
    for (int r = 0; r < 8; r++) {
        int ii = c0 + ty*8 + r;
        bool live = (ii < cnt);
        if (live) {
            uint2 hv = make_uint2(bpack(acc[r].x, acc[r].y), bpack(acc[r].z, acc[r].w));
            *reinterpret_cast<uint2*>(&g_hcb[(size_t)(b*NN + ii)*DD + tx*4]) = hv;
        }
        float pl = acc[r].x*alv.x + acc[r].y*alv.y + acc[r].z*alv.z + acc[r].w*alv.w;
        float pr = acc[r].x*arv.x + acc[r].y*arv.y + acc[r].z*arv.z + acc[r].w*arv.w;
#pragma unroll
        for (int off = 16; off; off >>= 1) {
            pl += __shfl_down_sync(0xffffffffu, pl, off);
            pr += __shfl_down_sync(0xffffffffu, pr, off);
        }
        if (tx == 0 && live) {
            g_eln[b*NN + ii] = bpack(exp2f(pl*LOG2E), exp2f(0.2f*pl*LOG2E));
            __nv_bfloat16 r1 = __float2bfloat16(exp2f(pr*LOG2E));
            __nv_bfloat16 r2 = __float2bfloat16(exp2f(0.2f*pr*LOG2E));
            g_er1c[b*NN + ii] = *reinterpret_cast<unsigned short*>(&r1);
            g_er2c[b*NN + ii] = *reinterpret_cast<unsigned short*>(&r2);
        }
    }
}

// ---------------- K3: 8 rows/block (2 waves), 0/1-adj IMAD nibbles ----------
__global__ __launch_bounds__(256) void k3_adjc(const int* __restrict__ adj) {
    int b = blockIdx.y;
    int cnt = g_cnt[b];
    int ii0 = blockIdx.x * 8;
    if (ii0 >= cnt) return;
    int pad = (cnt + 31) & ~31;
    int t = threadIdx.x, lane = t & 31;
    int nrows = min(8, cnt - ii0);

    __shared__ unsigned ubits[8][64];

#pragma unroll
    for (int h = 0; h < 2; h++) {
        const int4* rp[4];
#pragma unroll
        for (int r = 0; r < 4; r++) {
            int ir = g_act[b*NN + min(ii0 + h*4 + r, cnt - 1)];
            rp[r] = reinterpret_cast<const int4*>(adj + ((size_t)b*NN + ir)*NN);
        }
        int4 av[8];
#pragma unroll
        for (int r = 0; r < 4; r++) { av[r*2] = rp[r][t]; av[r*2+1] = rp[r][t + 256]; }

#pragma unroll
        for (int r = 0; r < 4; r++) {
#pragma unroll
            for (int q = 0; q < 2; q++) {
                int4 A = av[r*2 + q];
                unsigned nib = (unsigned)(A.x + (A.y << 1) + (A.z << 2) + (A.w << 3));
                unsigned v = nib << ((t & 7)*4);
                v |= __shfl_xor_sync(0xffffffffu, v, 1);
                v |= __shfl_xor_sync(0xffffffffu, v, 2);
                v |= __shfl_xor_sync(0xffffffffu, v, 4);
                if ((t & 7) == 0) ubits[h*4 + r][(q*256 + t) >> 3] = v;
            }
        }
    }
    __syncthreads();

    const int* actb = g_act + b*NN;
    unsigned* dst = g_adjc + ((size_t)b*NN + ii0)*NW;
    for (int jj = t; jj < pad; jj += 256) {
        int wsel = 0, bsel = 0;
        bool v = (jj < cnt);
        if (v) { int j = actb[jj]; wsel = j >> 5; bsel = j & 31; }
#pragma unroll
        for (int r = 0; r < 8; r++) {
            unsigned bit = v ? ((ubits[r][wsel] >> bsel) & 1u) : 0u;
            unsigned w = __ballot_sync(0xffffffffu, bit);
            if (lane == 0 && r < nrows) dst[(size_t)r*NW + (jj >> 5)] = w;
        }
    }
}

// ---------------- K4: exp-free bf16 tensor P@H, register-prefetched (R12) ---
__device__ __forceinline__ unsigned pmix(unsigned El1, unsigned El2,
                                         unsigned e1, unsigned e2, unsigned m) {
    return hmax2u(hmul2u(El1, e1), hmul2u(El2, e2)) & m;
}

__global__ __launch_bounds__(256,3) void k4_attn(void)
{
    __shared__ __align__(16) unsigned short Pp[2][64][PSTR];
    __shared__ __align__(16) unsigned short Hs[2][32][HSTR];
    __shared__ unsigned lutm[4];

    int b = blockIdx.z, sid = blockIdx.y;
    int cnt = g_cnt[b];
    int base = blockIdx.x * 64;
    if (base >= cnt) return;

    int tid = threadIdx.x, lane = tid & 31, wid = tid >> 5;
    int mw = wid >> 2, nw = wid & 3, wd = nw*32;
    if (tid < 4) lutm[tid] = ((tid & 1) ? 0xFFFFu : 0u) | ((tid & 2) ? 0xFFFF0000u : 0u);

    int nch = (cnt + 31) >> 5;
    int cs  = (nch + SPLIT - 1) / SPLIT;
    int jc0 = min(nch, sid * cs);
    int jc1 = min(nch, jc0 + cs);

    int prow = tid >> 2, jq = (tid & 3) * 8;
    int iw = min(base + prow, cnt - 1);
    unsigned eln = g_eln[b*NN + iw];
    unsigned El1 = __byte_perm(eln, eln, 0x1010);
    unsigned El2 = __byte_perm(eln, eln, 0x3232);
    const unsigned* adjp = g_adjc + ((size_t)b*NN + iw)*NW;
    const unsigned short* er1b = g_er1c + b*NN;
    const unsigned short* er2b = g_er2c + b*NN;

    int hrow = tid >> 3, hseg = (tid & 7) * 16;
    const unsigned short* hsrc0 = g_hcb + (size_t)b*NN*DD;

    float4 acc[2][4]; float4 ps[2];
#pragma unroll
    for (int mt = 0; mt < 2; mt++) {
        ps[mt] = make_float4(0.f,0.f,0.f,0.f);
#pragma unroll
        for (int nt = 0; nt < 4; nt++) acc[mt][nt] = make_float4(0.f,0.f,0.f,0.f);
    }

    unsigned Pbase = (unsigned)__cvta_generic_to_shared(&Pp[0][0][0]);
    unsigned Hbase = (unsigned)__cvta_generic_to_shared(&Hs[0][0][0]);
    unsigned aaddr = Pbase + (unsigned)((mw*32 + (lane & 15))*PSTR*2 + ((lane >> 4) & 1)*16);
    unsigned baddr = Hbase + (unsigned)(((((lane >> 3) & 1)*8) + (lane & 7))*HSTR*2
                                        + (wd + ((lane >> 4) & 1)*8)*2);
    unsigned pdst = Pbase + (unsigned)(prow*PSTR*2 + jq*2);
    unsigned hdst = Hbase + (unsigned)(hrow*HSTR*2 + hseg*2);
    const unsigned ONES = 0x3F803F80u;

    __syncthreads();

    if (jc0 < jc1) {
        unsigned w = adjp[jc0] >> jq;
        uint4 e1 = *reinterpret_cast<const uint4*>(er1b + jc0*32 + jq);
        uint4 e2 = *reinterpret_cast<const uint4*>(er2b + jc0*32 + jq);
        uint4 o;
        o.x = pmix(El1, El2, e1.x, e2.x, lutm[w & 3]);
        o.y = pmix(El1, El2, e1.y, e2.y, lutm[(w >> 2) & 3]);
        o.z = pmix(El1, El2, e1.z, e2.z, lutm[(w >> 4) & 3]);
        o.w = pmix(El1, El2, e1.w, e2.w, lutm[(w >> 6) & 3]);
        asm volatile("st.shared.v4.b32 [%0], {%1,%2,%3,%4};"
                     :: "r"(pdst), "r"(o.x), "r"(o.y), "r"(o.z), "r"(o.w));
        const unsigned short* src = hsrc0 + ((size_t)(jc0*32 + hrow))*DD + hseg;
        CP_ASYNC16(hdst, src);
        CP_ASYNC16(hdst + 16, src + 8);
        CP_COMMIT;
    }

    unsigned pf_w = 0;
    uint4 pf_e1 = make_uint4(0,0,0,0), pf_e2 = make_uint4(0,0,0,0);
    if (jc0 + 1 < jc1) {
        pf_w  = adjp[jc0 + 1];
        pf_e1 = *reinterpret_cast<const uint4*>(er1b + (jc0+1)*32 + jq);
        pf_e2 = *reinterpret_cast<const uint4*>(er2b + (jc0+1)*32 + jq);
    }

    for (int jc = jc0; jc < jc1; jc++) {
        int cur = (jc - jc0) & 1, nxt = cur ^ 1;
        CP_WAIT0;
        __syncthreads();

        if (jc + 1 < jc1) {
            unsigned w = pf_w >> jq;
            uint4 o;
            o.x = pmix(El1, El2, pf_e1.x, pf_e2.x, lutm[w & 3]);
            o.y = pmix(El1, El2, pf_e1.y, pf_e2.y, lutm[(w >> 2) & 3]);
            o.z = pmix(El1, El2, pf_e1.z, pf_e2.z, lutm[(w >> 4) & 3]);
            o.w = pmix(El1, El2, pf_e1.w, pf_e2.w, lutm[(w >> 6) & 3]);
            asm volatile("st.shared.v4.b32 [%0], {%1,%2,%3,%4};"
                         :: "r"(pdst + nxt*PBUFB), "r"(o.x), "r"(o.y), "r"(o.z), "r"(o.w));
            const unsigned short* src = hsrc0 + ((size_t)((jc+1)*32 + hrow))*DD + hseg;
            CP_ASYNC16(hdst + nxt*HBUFB, src);
            CP_ASYNC16(hdst + nxt*HBUFB + 16, src + 8);
            CP_COMMIT;
            if (jc + 2 < jc1) {
                pf_w  = adjp[jc + 2];
                pf_e1 = *reinterpret_cast<const uint4*>(er1b + (jc+2)*32 + jq);
                pf_e2 = *reinterpret_cast<const uint4*>(er2b + (jc+2)*32 + jq);
            }
        }

        unsigned pa = aaddr + cur*PBUFB;
        unsigned hb = baddr + cur*HBUFB;
#pragma unroll
        for (int ks = 0; ks < 2; ks++) {
            unsigned bf[8];
            ldsm_x4_t(bf[0], bf[1], bf[2], bf[3], hb + ks*16*HSTR*2);
            ldsm_x4_t(bf[4], bf[5], bf[6], bf[7], hb + ks*16*HSTR*2 + 32);
            unsigned a0[4], a1[4];
            ldsm_x4(a0[0], a0[1], a0[2], a0[3], pa + ks*32);
            ldsm_x4(a1[0], a1[1], a1[2], a1[3], pa + 16*PSTR*2 + ks*32);
#pragma unroll
            for (int nt = 0; nt < 4; nt++) {
                mma_bf16(acc[0][nt], a0[0],a0[1],a0[2],a0[3], bf[nt*2], bf[nt*2+1]);
                mma_bf16(acc[1][nt], a1[0],a1[1],a1[2],a1[3], bf[nt*2], bf[nt*2+1]);
            }
            if (nw == 0) {
                mma_bf16(ps[0], a0[0],a0[1],a0[2],a0[3], ONES, ONES);
                mma_bf16(ps[1], a1[0],a1[1],a1[2],a1[3], ONES, ONES);
            }
        }
    }

    int gid = lane >> 2, tig = lane & 3;
    if (nw == 0 && tig == 0) {
#pragma unroll
        for (int mt = 0; mt < 2; mt++) {
            int i0 = base + mw*32 + mt*16 + gid;
            g_psumP[sid][b*NN + i0]     = ps[mt].x;
            g_psumP[sid][b*NN + i0 + 8] = ps[mt].z;
        }
    }

    float* pb = g_pacc + (size_t)sid*BB*NN*DD + (size_t)b*NN*DD;
#pragma unroll
    for (int mt = 0; mt < 2; mt++) {
        int i0 = base + mw*32 + mt*16 + gid;
#pragma unroll
        for (int nt = 0; nt < 4; nt++) {
            int d0 = wd + nt*8 + 2*tig;
            *reinterpret_cast<float2*>(&pb[(size_t)i0*DD + d0]) =
                make_float2(acc[mt][nt].x, acc[mt][nt].y);
            *reinterpret_cast<float2*>(&pb[(size_t)(i0+8)*DD + d0]) =
                make_float2(acc[mt][nt].z, acc[mt][nt].w);
        }
    }
}

// ---------------- K5: batched-MLP reduce + normalize + residual + LN --------
__global__ __launch_bounds__(128) void k5_finish(
    const float* __restrict__ x, const float* __restrict__ gamma,
    const float* __restrict__ beta, float* __restrict__ out)
{
    int b = blockIdx.y;
    int cnt = g_cnt[b];
    int lane = threadIdx.x & 31, wid = threadIdx.x >> 5;
    int base_n = blockIdx.x * 8 + wid * 2;

    int g0 = b*NN + base_n, g1 = g0 + 1;

    // --- phase 1: independent loads, all in flight together ---
    int ii0 = g_posm[g0];
    int ii1 = g_posm[g1];
    float4 x0 = *reinterpret_cast<const float4*>(x + (size_t)g0*DD + lane*4);
    float4 x1 = *reinterpret_cast<const float4*>(x + (size_t)g1*DD + lane*4);
    float4 gv = *reinterpret_cast<const float4*>(gamma + lane*4);
    float4 bv = *reinterpret_cast<const float4*>(beta  + lane*4);

    // clamped indices so pacc/psum loads are unconditional (dead for masked)
    int c0i = (ii0 >= 0) ? ii0 : 0;
    int c1i = (ii1 >= 0) ? ii1 : 0;
    const float4* p00 = reinterpret_cast<const float4*>(g_pacc + ((size_t)b*NN + c0i)*DD);
    const float4* p01 = reinterpret_cast<const float4*>(g_pacc + (size_t)BB*NN*DD + ((size_t)b*NN + c0i)*DD);
    const float4* p10 = reinterpret_cast<const float4*>(g_pacc + ((size_t)b*NN + c1i)*DD);
    const float4* p11 = reinterpret_cast<const float4*>(g_pacc + (size_t)BB*NN*DD + ((size_t)b*NN + c1i)*DD);
    float4 t00 = p00[lane], t01 = p01[lane];
    float4 t10 = p10[lane], t11 = p11[lane];
    float tot0 = g_psumP[0][b*NN + c0i] + g_psumP[1][b*NN + c0i];
    float tot1 = g_psumP[0][b*NN + c1i] + g_psumP[1][b*NN + c1i];

    float4 aR[2], xR[2]; float totR[2]; int iiR[2], gR[2];
    aR[0] = make_float4(t00.x+t01.x, t00.y+t01.y, t00.z+t01.z, t00.w+t01.w);
    aR[1] = make_float4(t10.x+t11.x, t10.y+t11.y, t10.z+t11.z, t10.w+t11.w);
    xR[0] = x0; xR[1] = x1; totR[0] = tot0; totR[1] = tot1;
    iiR[0] = ii0; iiR[1] = ii1; gR[0] = g0; gR[1] = g1;

    // --- phase 2: compute both rows ---
#pragma unroll
    for (int r = 0; r < 2; r++) {
        if (iiR[r] < 0) {   // masked row -> exactly beta
            *reinterpret_cast<float4*>(out + (size_t)gR[r]*DD + lane*4) = bv;
            continue;
        }
        float4 a = aR[r];
        float inv;
        if (totR[r] > 0.f) {
            inv = 1.f / totR[r];
        } else {
            // exact fallback: zero-neighbor row -> uniform softmax over all N
            a = make_float4(0.f,0.f,0.f,0.f);
            const unsigned short* hb = g_hcb + (size_t)b*NN*DD + lane*4;
            for (int jj = 0; jj < cnt; jj++) {
                uint2 hv = *reinterpret_cast<const uint2*>(hb + (size_t)jj*DD);
                float2 f0 = __bfloat1622float2(*reinterpret_cast<__nv_bfloat162*>(&hv.x));
                float2 f1 = __bfloat1622float2(*reinterpret_cast<__nv_bfloat162*>(&hv.y));
                a.x += f0.x; a.y += f0.y; a.z += f1.x; a.w += f1.y;
            }
            inv = 1.f / (float)NN;
        }

        float4 v;
        v.x = a.x*inv + xR[r].x;  v.y = a.y*inv + xR[r].y;
        v.z = a.z*inv + xR[r].z;  v.w = a.w*inv + xR[r].w;
        float s1 = v.x + v.y + v.z + v.w;
        float s2 = v.x*v.x + v.y*v.y + v.z*v.z + v.w*v.w;
#pragma unroll
        for (int off = 16; off; off >>= 1) {
            s1 += __shfl_xor_sync(0xffffffffu, s1, off);
            s2 += __shfl_xor_sync(0xffffffffu, s2, off);
        }
        float mu  = s1 * (1.f/128.f);
        float var = s2 * (1.f/128.f) - mu*mu;
        float rs  = rsqrtf(var + 1e-5f);
        float4 o;
        o.x = (v.x - mu)*rs*gv.x + bv.x;
        o.y = (v.y - mu)*rs*gv.y + bv.y;
        o.z = (v.z - mu)*rs*gv.z + bv.z;
        o.w = (v.w - mu)*rs*gv.w + bv.w;
        *reinterpret_cast<float4*>(out + (size_t)gR[r]*DD + lane*4) = o;
    }
}

// ---------------- launcher ---------------------------------------------------
extern "C" void kernel_launch(void* const* d_in, const int* in_sizes, int n_in,
                              void* d_out, int out_size) {
    const float* x     = (const float*)d_in[0];
    const int*   adj   = (const int*)  d_in[1];
    const int*   nm    = (const int*)  d_in[2];
    const float* W     = (const float*)d_in[3];
    const float* a_l   = (const float*)d_in[4];
    const float* a_r   = (const float*)d_in[5];
    const float* gamma = (const float*)d_in[6];
    const float* beta  = (const float*)d_in[7];
    float* out = (float*)d_out;

    k1_compact<<<BB, 256>>>(nm);
    k2_gemm<<<dim3(NN/32, BB), 128>>>(x, W, a_l, a_r);
    k3_adjc<<<dim3(NN/8, BB), 256>>>(adj);
    k4_attn<<<dim3(NN/64, SPLIT, BB), 256>>>();
    k5_finish<<<dim3(NN/8, BB), 128>>>(x, gamma, beta, out);
}

// round 17
// speedup vs baseline: 1.2214x; 1.2214x over previous
#include <cuda_runtime.h>
#include <cuda_bf16.h>
#include <cstdint>

#define BB 8
#define NN 2048
#define DD 128
#define LOG2E 1.44269504f
#define NW (NN/32)
#define SPLIT 2
#define PSTR 40      // P smem row stride (bf16)
#define HSTR 136     // H smem row stride (bf16)
#define PBUFB (64*PSTR*2)
#define HBUFB (32*HSTR*2)

// ---------------- device scratch ----------------
__device__ unsigned short g_hcb [BB*NN*DD];   // compacted h, bf16 (padded rows 0)
__device__ unsigned       g_eln [BB*NN];      // packed (bf16 e^{.2el}<<16)|bf16 e^{el}
__device__ unsigned short g_er1c[BB*NN];      // bf16 e^{er}
__device__ unsigned short g_er2c[BB*NN];      // bf16 e^{.2er}
__device__ int            g_act [BB*NN];
__device__ int            g_posm[BB*NN];
__device__ int            g_cnt [BB];
__device__ unsigned       g_adjc[(size_t)BB*NN*NW];
__device__ float          g_pacc[(size_t)SPLIT*BB*NN*DD];
__device__ float          g_psumP[SPLIT][BB*NN];

// ---- stream/event for k2||k3 overlap (created once at load; no device mem) -
static cudaStream_t g_s2 = nullptr;
static cudaEvent_t  g_evF = nullptr, g_evJ = nullptr;
static struct StreamInit {
    StreamInit() {
        cudaStreamCreateWithFlags(&g_s2, cudaStreamNonBlocking);
        cudaEventCreateWithFlags(&g_evF, cudaEventDisableTiming);
        cudaEventCreateWithFlags(&g_evJ, cudaEventDisableTiming);
    }
} g_streamInit;

// ---- helpers ----
__device__ __forceinline__ unsigned hmul2u(unsigned a, unsigned b) {
    __nv_bfloat162 r = __hmul2(*reinterpret_cast<__nv_bfloat162*>(&a),
                               *reinterpret_cast<__nv_bfloat162*>(&b));
    return *reinterpret_cast<unsigned*>(&r);
}
__device__ __forceinline__ unsigned hmax2u(unsigned a, unsigned b) {
    __nv_bfloat162 r = __hmax2(*reinterpret_cast<__nv_bfloat162*>(&a),
                               *reinterpret_cast<__nv_bfloat162*>(&b));
    return *reinterpret_cast<unsigned*>(&r);
}
__device__ __forceinline__ unsigned bpack(float x, float y) {
    __nv_bfloat162 r = __float22bfloat162_rn(make_float2(x, y));
    return *reinterpret_cast<unsigned*>(&r);
}
__device__ __forceinline__ void ldsm_x4(unsigned& r0, unsigned& r1,
                                        unsigned& r2, unsigned& r3, unsigned addr) {
    asm volatile("ldmatrix.sync.aligned.m8n8.x4.shared.b16 {%0,%1,%2,%3}, [%4];"
                 : "=r"(r0), "=r"(r1), "=r"(r2), "=r"(r3) : "r"(addr));
}
__device__ __forceinline__ void ldsm_x4_t(unsigned& r0, unsigned& r1,
                                          unsigned& r2, unsigned& r3, unsigned addr) {
    asm volatile("ldmatrix.sync.aligned.m8n8.x4.trans.shared.b16 {%0,%1,%2,%3}, [%4];"
                 : "=r"(r0), "=r"(r1), "=r"(r2), "=r"(r3) : "r"(addr));
}
__device__ __forceinline__ void mma_bf16(float4& d, unsigned a0, unsigned a1,
                                         unsigned a2, unsigned a3,
                                         unsigned b0, unsigned b1) {
    asm volatile("mma.sync.aligned.m16n8k16.row.col.f32.bf16.bf16.f32 "
        "{%0,%1,%2,%3}, {%4,%5,%6,%7}, {%8,%9}, {%0,%1,%2,%3};"
        : "+f"(d.x), "+f"(d.y), "+f"(d.z), "+f"(d.w)
        : "r"(a0), "r"(a1), "r"(a2), "r"(a3), "r"(b0), "r"(b1));
}
#define CP_ASYNC16(dst, src) \
    asm volatile("cp.async.cg.shared.global [%0], [%1], 16;" :: "r"(dst), "l"(src))
#define CP_COMMIT asm volatile("cp.async.commit_group;" ::: "memory")
#define CP_WAIT0  asm volatile("cp.async.wait_group 0;" ::: "memory")

// ---------------- K1: deterministic compaction ----------------
__global__ void k1_compact(const int* __restrict__ nm) {
    int b = blockIdx.x, t = threadIdx.x;
    __shared__ int part[256];
    const int* m = nm + b*NN;
    int base = t*8, flags[8], c = 0;
#pragma unroll
    for (int k = 0; k < 8; k++) { flags[k] = (m[base+k] != 0); c += flags[k]; }
    part[t] = c; __syncthreads();
    for (int off = 1; off < 256; off <<= 1) {
        int add = (t >= off) ? part[t-off] : 0;
        __syncthreads(); part[t] += add; __syncthreads();
    }
    int pos = part[t] - c;
#pragma unroll
    for (int k = 0; k < 8; k++) {
        if (flags[k]) { g_act[b*NN + pos] = base + k; g_posm[b*NN + base + k] = pos; pos++; }
        else g_posm[b*NN + base + k] = -1;
    }
    if (t == 255) g_cnt[b] = part[255];
}

// ---------------- K2: h = x_active @ W over compacted rows ------------------
__global__ __launch_bounds__(128) void k2_gemm(
    const float* __restrict__ x, const float* __restrict__ W,
    const float* __restrict__ a_l, const float* __restrict__ a_r)
{
    int b = blockIdx.y;
    int cnt = g_cnt[b];
    int c0 = blockIdx.x * 32;
    if (c0 >= cnt) return;

    __shared__ float xs[32][DD];
    int tid = threadIdx.x, tx = tid & 31, ty = tid >> 5;

#pragma unroll 4
    for (int i = 0; i < 32; i++) {
        int ii = c0 + i;
        int row = g_act[b*NN + ((ii < cnt) ? ii : (cnt - 1))];
        xs[i][tid] = x[((size_t)b*NN + row)*DD + tid];
    }
    __syncthreads();

    float4 acc[8];
#pragma unroll
    for (int r = 0; r < 8; r++) acc[r] = make_float4(0.f,0.f,0.f,0.f);

    const float4* W4 = reinterpret_cast<const float4*>(W);
#pragma unroll 4
    for (int k = 0; k < DD; k++) {
        float4 w4 = W4[k*32 + tx];
#pragma unroll
        for (int r = 0; r < 8; r++) {
            float xv = xs[ty*8 + r][k];
            acc[r].x += xv*w4.x; acc[r].y += xv*w4.y;
            acc[r].z += xv*w4.z; acc[r].w += xv*w4.w;
        }
    }

    float4 alv = *reinterpret_cast<const float4*>(a_l + tx*4);
    float4 arv = *reinterpret_cast<const float4*>(a_r + tx*4);
#pragma unroll
    for (int r = 0; r < 8; r++) {
        int ii = c0 + ty*8 + r;
        bool live = (ii < cnt);
        if (live) {
            uint2 hv = make_uint2(bpack(acc[r].x, acc[r].y), bpack(acc[r].z, acc[r].w));
            *reinterpret_cast<uint2*>(&g_hcb[(size_t)(b*NN + ii)*DD + tx*4]) = hv;
        }
        float pl = acc[r].x*alv.x + acc[r].y*alv.y + acc[r].z*alv.z + acc[r].w*alv.w;
        float pr = acc[r].x*arv.x + acc[r].y*arv.y + acc[r].z*arv.z + acc[r].w*arv.w;
#pragma unroll
        for (int off = 16; off; off >>= 1) {
            pl += __shfl_down_sync(0xffffffffu, pl, off);
            pr += __shfl_down_sync(0xffffffffu, pr, off);
        }
        if (tx == 0 && live) {
            g_eln[b*NN + ii] = bpack(exp2f(pl*LOG2E), exp2f(0.2f*pl*LOG2E));
            __nv_bfloat16 r1 = __float2bfloat16(exp2f(pr*LOG2E));
            __nv_bfloat16 r2 = __float2bfloat16(exp2f(0.2f*pr*LOG2E));
            g_er1c[b*NN + ii] = *reinterpret_cast<unsigned short*>(&r1);
            g_er2c[b*NN + ii] = *reinterpret_cast<unsigned short*>(&r2);
        }
    }
}

// ---------------- K3: 8 rows/block (2 waves), 0/1-adj IMAD nibbles ----------
__global__ __launch_bounds__(256) void k3_adjc(const int* __restrict__ adj) {
    int b = blockIdx.y;
    int cnt = g_cnt[b];
    int ii0 = blockIdx.x * 8;
    if (ii0 >= cnt) return;
    int pad = (cnt + 31) & ~31;
    int t = threadIdx.x, lane = t & 31;
    int nrows = min(8, cnt - ii0);

    __shared__ unsigned ubits[8][64];

#pragma unroll
    for (int h = 0; h < 2; h++) {
        const int4* rp[4];
#pragma unroll
        for (int r = 0; r < 4; r++) {
            int ir = g_act[b*NN + min(ii0 + h*4 + r, cnt - 1)];
            rp[r] = reinterpret_cast<const int4*>(adj + ((size_t)b*NN + ir)*NN);
        }
        int4 av[8];
#pragma unroll
        for (int r = 0; r < 4; r++) { av[r*2] = rp[r][t]; av[r*2+1] = rp[r][t + 256]; }

#pragma unroll
        for (int r = 0; r < 4; r++) {
#pragma unroll
            for (int q = 0; q < 2; q++) {
                int4 A = av[r*2 + q];
                unsigned nib = (unsigned)(A.x + (A.y << 1) + (A.z << 2) + (A.w << 3));
                unsigned v = nib << ((t & 7)*4);
                v |= __shfl_xor_sync(0xffffffffu, v, 1);
                v |= __shfl_xor_sync(0xffffffffu, v, 2);
                v |= __shfl_xor_sync(0xffffffffu, v, 4);
                if ((t & 7) == 0) ubits[h*4 + r][(q*256 + t) >> 3] = v;
            }
        }
    }
    __syncthreads();

    const int* actb = g_act + b*NN;
    unsigned* dst = g_adjc + ((size_t)b*NN + ii0)*NW;
    for (int jj = t; jj < pad; jj += 256) {
        int wsel = 0, bsel = 0;
        bool v = (jj < cnt);
        if (v) { int j = actb[jj]; wsel = j >> 5; bsel = j & 31; }
#pragma unroll
        for (int r = 0; r < 8; r++) {
            unsigned bit = v ? ((ubits[r][wsel] >> bsel) & 1u) : 0u;
            unsigned w = __ballot_sync(0xffffffffu, bit);
            if (lane == 0 && r < nrows) dst[(size_t)r*NW + (jj >> 5)] = w;
        }
    }
}

// ---------------- K4: exp-free bf16 tensor P@H, register-prefetched (R12) ---
__device__ __forceinline__ unsigned pmix(unsigned El1, unsigned El2,
                                         unsigned e1, unsigned e2, unsigned m) {
    return hmax2u(hmul2u(El1, e1), hmul2u(El2, e2)) & m;
}

__global__ __launch_bounds__(256,3) void k4_attn(void)
{
    __shared__ __align__(16) unsigned short Pp[2][64][PSTR];
    __shared__ __align__(16) unsigned short Hs[2][32][HSTR];
    __shared__ unsigned lutm[4];

    int b = blockIdx.z, sid = blockIdx.y;
    int cnt = g_cnt[b];
    int base = blockIdx.x * 64;
    if (base >= cnt) return;

    int tid = threadIdx.x, lane = tid & 31, wid = tid >> 5;
    int mw = wid >> 2, nw = wid & 3, wd = nw*32;
    if (tid < 4) lutm[tid] = ((tid & 1) ? 0xFFFFu : 0u) | ((tid & 2) ? 0xFFFF0000u : 0u);

    int nch = (cnt + 31) >> 5;
    int cs  = (nch + SPLIT - 1) / SPLIT;
    int jc0 = min(nch, sid * cs);
    int jc1 = min(nch, jc0 + cs);

    int prow = tid >> 2, jq = (tid & 3) * 8;
    int iw = min(base + prow, cnt - 1);
    unsigned eln = g_eln[b*NN + iw];
    unsigned El1 = __byte_perm(eln, eln, 0x1010);
    unsigned El2 = __byte_perm(eln, eln, 0x3232);
    const unsigned* adjp = g_adjc + ((size_t)b*NN + iw)*NW;
    const unsigned short* er1b = g_er1c + b*NN;
    const unsigned short* er2b = g_er2c + b*NN;

    int hrow = tid >> 3, hseg = (tid & 7) * 16;
    const unsigned short* hsrc0 = g_hcb + (size_t)b*NN*DD;

    float4 acc[2][4]; float4 ps[2];
#pragma unroll
    for (int mt = 0; mt < 2; mt++) {
        ps[mt] = make_float4(0.f,0.f,0.f,0.f);
#pragma unroll
        for (int nt = 0; nt < 4; nt++) acc[mt][nt] = make_float4(0.f,0.f,0.f,0.f);
    }

    unsigned Pbase = (unsigned)__cvta_generic_to_shared(&Pp[0][0][0]);
    unsigned Hbase = (unsigned)__cvta_generic_to_shared(&Hs[0][0][0]);
    unsigned aaddr = Pbase + (unsigned)((mw*32 + (lane & 15))*PSTR*2 + ((lane >> 4) & 1)*16);
    unsigned baddr = Hbase + (unsigned)(((((lane >> 3) & 1)*8) + (lane & 7))*HSTR*2
                                        + (wd + ((lane >> 4) & 1)*8)*2);
    unsigned pdst = Pbase + (unsigned)(prow*PSTR*2 + jq*2);
    unsigned hdst = Hbase + (unsigned)(hrow*HSTR*2 + hseg*2);
    const unsigned ONES = 0x3F803F80u;

    __syncthreads();

    if (jc0 < jc1) {
        unsigned w = adjp[jc0] >> jq;
        uint4 e1 = *reinterpret_cast<const uint4*>(er1b + jc0*32 + jq);
        uint4 e2 = *reinterpret_cast<const uint4*>(er2b + jc0*32 + jq);
        uint4 o;
        o.x = pmix(El1, El2, e1.x, e2.x, lutm[w & 3]);
        o.y = pmix(El1, El2, e1.y, e2.y, lutm[(w >> 2) & 3]);
        o.z = pmix(El1, El2, e1.z, e2.z, lutm[(w >> 4) & 3]);
        o.w = pmix(El1, El2, e1.w, e2.w, lutm[(w >> 6) & 3]);
        asm volatile("st.shared.v4.b32 [%0], {%1,%2,%3,%4};"
                     :: "r"(pdst), "r"(o.x), "r"(o.y), "r"(o.z), "r"(o.w));
        const unsigned short* src = hsrc0 + ((size_t)(jc0*32 + hrow))*DD + hseg;
        CP_ASYNC16(hdst, src);
        CP_ASYNC16(hdst + 16, src + 8);
        CP_COMMIT;
    }

    unsigned pf_w = 0;
    uint4 pf_e1 = make_uint4(0,0,0,0), pf_e2 = make_uint4(0,0,0,0);
    if (jc0 + 1 < jc1) {
        pf_w  = adjp[jc0 + 1];
        pf_e1 = *reinterpret_cast<const uint4*>(er1b + (jc0+1)*32 + jq);
        pf_e2 = *reinterpret_cast<const uint4*>(er2b + (jc0+1)*32 + jq);
    }

    for (int jc = jc0; jc < jc1; jc++) {
        int cur = (jc - jc0) & 1, nxt = cur ^ 1;
        CP_WAIT0;
        __syncthreads();

        if (jc + 1 < jc1) {
            unsigned w = pf_w >> jq;
            uint4 o;
            o.x = pmix(El1, El2, pf_e1.x, pf_e2.x, lutm[w & 3]);
            o.y = pmix(El1, El2, pf_e1.y, pf_e2.y, lutm[(w >> 2) & 3]);
            o.z = pmix(El1, El2, pf_e1.z, pf_e2.z, lutm[(w >> 4) & 3]);
            o.w = pmix(El1, El2, pf_e1.w, pf_e2.w, lutm[(w >> 6) & 3]);
            asm volatile("st.shared.v4.b32 [%0], {%1,%2,%3,%4};"
                         :: "r"(pdst + nxt*PBUFB), "r"(o.x), "r"(o.y), "r"(o.z), "r"(o.w));
            const unsigned short* src = hsrc0 + ((size_t)((jc+1)*32 + hrow))*DD + hseg;
            CP_ASYNC16(hdst + nxt*HBUFB, src);
            CP_ASYNC16(hdst + nxt*HBUFB + 16, src + 8);
            CP_COMMIT;
            if (jc + 2 < jc1) {
                pf_w  = adjp[jc + 2];
                pf_e1 = *reinterpret_cast<const uint4*>(er1b + (jc+2)*32 + jq);
                pf_e2 = *reinterpret_cast<const uint4*>(er2b + (jc+2)*32 + jq);
            }
        }

        unsigned pa = aaddr + cur*PBUFB;
        unsigned hb = baddr + cur*HBUFB;
#pragma unroll
        for (int ks = 0; ks < 2; ks++) {
            unsigned bf[8];
            ldsm_x4_t(bf[0], bf[1], bf[2], bf[3], hb + ks*16*HSTR*2);
            ldsm_x4_t(bf[4], bf[5], bf[6], bf[7], hb + ks*16*HSTR*2 + 32);
            unsigned a0[4], a1[4];
            ldsm_x4(a0[0], a0[1], a0[2], a0[3], pa + ks*32);
            ldsm_x4(a1[0], a1[1], a1[2], a1[3], pa + 16*PSTR*2 + ks*32);
#pragma unroll
            for (int nt = 0; nt < 4; nt++) {
                mma_bf16(acc[0][nt], a0[0],a0[1],a0[2],a0[3], bf[nt*2], bf[nt*2+1]);
                mma_bf16(acc[1][nt], a1[0],a1[1],a1[2],a1[3], bf[nt*2], bf[nt*2+1]);
            }
            if (nw == 0) {
                mma_bf16(ps[0], a0[0],a0[1],a0[2],a0[3], ONES, ONES);
                mma_bf16(ps[1], a1[0],a1[1],a1[2],a1[3], ONES, ONES);
            }
        }
    }

    int gid = lane >> 2, tig = lane & 3;
    if (nw == 0 && tig == 0) {
#pragma unroll
        for (int mt = 0; mt < 2; mt++) {
            int i0 = base + mw*32 + mt*16 + gid;
            g_psumP[sid][b*NN + i0]     = ps[mt].x;
            g_psumP[sid][b*NN + i0 + 8] = ps[mt].z;
        }
    }

    float* pb = g_pacc + (size_t)sid*BB*NN*DD + (size_t)b*NN*DD;
#pragma unroll
    for (int mt = 0; mt < 2; mt++) {
        int i0 = base + mw*32 + mt*16 + gid;
#pragma unroll
        for (int nt = 0; nt < 4; nt++) {
            int d0 = wd + nt*8 + 2*tig;
            *reinterpret_cast<float2*>(&pb[(size_t)i0*DD + d0]) =
                make_float2(acc[mt][nt].x, acc[mt][nt].y);
            *reinterpret_cast<float2*>(&pb[(size_t)(i0+8)*DD + d0]) =
                make_float2(acc[mt][nt].z, acc[mt][nt].w);
        }
    }
}

// ---------------- K5: reduce + normalize + residual + LN (R12 form) ---------
__global__ __launch_bounds__(128) void k5_finish(
    const float* __restrict__ x, const float* __restrict__ gamma,
    const float* __restrict__ beta, float* __restrict__ out)
{
    int b = blockIdx.y;
    int cnt = g_cnt[b];
    int lane = threadIdx.x & 31, wid = threadIdx.x >> 5;
    int base_n = blockIdx.x * 8 + wid * 2;

    float4 gv = *reinterpret_cast<const float4*>(gamma + lane*4);
    float4 bv = *reinterpret_cast<const float4*>(beta  + lane*4);

#pragma unroll
    for (int r = 0; r < 2; r++) {
        int n = base_n + r;
        int g = b*NN + n;
        int ii = g_posm[g];
        if (ii < 0) {   // masked row -> exactly beta
            *reinterpret_cast<float4*>(out + (size_t)g*DD + lane*4) = bv;
            continue;
        }

        float4 a = make_float4(0.f,0.f,0.f,0.f);
        float tot = 0.f;
#pragma unroll
        for (int s = 0; s < SPLIT; s++) {
            const float4* pp = reinterpret_cast<const float4*>(
                g_pacc + (size_t)s*BB*NN*DD + ((size_t)b*NN + ii)*DD);
            float4 t = pp[lane];
            a.x += t.x; a.y += t.y; a.z += t.z; a.w += t.w;
            tot += g_psumP[s][b*NN + ii];
        }

        float inv;
        if (tot > 0.f) {
            inv = 1.f / tot;
        } else {
            // exact fallback: zero-neighbor row -> uniform softmax over all N
            a = make_float4(0.f,0.f,0.f,0.f);
            const unsigned short* hb = g_hcb + (size_t)b*NN*DD + lane*4;
            for (int jj = 0; jj < cnt; jj++) {
                uint2 hv = *reinterpret_cast<const uint2*>(hb + (size_t)jj*DD);
                float2 f0 = __bfloat1622float2(*reinterpret_cast<__nv_bfloat162*>(&hv.x));
                float2 f1 = __bfloat1622float2(*reinterpret_cast<__nv_bfloat162*>(&hv.y));
                a.x += f0.x; a.y += f0.y; a.z += f1.x; a.w += f1.y;
            }
            inv = 1.f / (float)NN;
        }

        float4 x4 = *reinterpret_cast<const float4*>(x + (size_t)g*DD + lane*4);
        float4 v;
        v.x = a.x*inv + x4.x;  v.y = a.y*inv + x4.y;
        v.z = a.z*inv + x4.z;  v.w = a.w*inv + x4.w;
        float s1 = v.x + v.y + v.z + v.w;
        float s2 = v.x*v.x + v.y*v.y + v.z*v.z + v.w*v.w;
#pragma unroll
        for (int off = 16; off; off >>= 1) {
            s1 += __shfl_xor_sync(0xffffffffu, s1, off);
            s2 += __shfl_xor_sync(0xffffffffu, s2, off);
        }
        float mu  = s1 * (1.f/128.f);
        float var = s2 * (1.f/128.f) - mu*mu;
        float rs  = rsqrtf(var + 1e-5f);
        float4 o;
        o.x = (v.x - mu)*rs*gv.x + bv.x;
        o.y = (v.y - mu)*rs*gv.y + bv.y;
        o.z = (v.z - mu)*rs*gv.z + bv.z;
        o.w = (v.w - mu)*rs*gv.w + bv.w;
        *reinterpret_cast<float4*>(out + (size_t)g*DD + lane*4) = o;
    }
}

// ---------------- launcher: k1 -> {k2 || k3} -> k4 -> k5 ---------------------
extern "C" void kernel_launch(void* const* d_in, const int* in_sizes, int n_in,
                              void* d_out, int out_size) {
    const float* x     = (const float*)d_in[0];
    const int*   adj   = (const int*)  d_in[1];
    const int*   nm    = (const int*)  d_in[2];
    const float* W     = (const float*)d_in[3];
    const float* a_l   = (const float*)d_in[4];
    const float* a_r   = (const float*)d_in[5];
    const float* gamma = (const float*)d_in[6];
    const float* beta  = (const float*)d_in[7];
    float* out = (float*)d_out;

    k1_compact<<<BB, 256>>>(nm);

    // fork: k2 on side stream, k3 on main stream (independent of each other)
    cudaEventRecord(g_evF, 0);
    cudaStreamWaitEvent(g_s2, g_evF, 0);
    k2_gemm<<<dim3(NN/32, BB), 128, 0, g_s2>>>(x, W, a_l, a_r);
    cudaEventRecord(g_evJ, g_s2);

    k3_adjc<<<dim3(NN/8, BB), 256>>>(adj);

    // join: k4 needs both k2 (h, exps) and k3 (adj bitmask)
    cudaStreamWaitEvent(0, g_evJ, 0);
    k4_attn<<<dim3(NN/64, SPLIT, BB), 256>>>();
    k5_finish<<<dim3(NN/8, BB), 128>>>(x, gamma, beta, out);
}